// round 12
// baseline (speedup 1.0000x reference)
#include <cuda_runtime.h>
#include <cuda_bf16.h>
#include <stdint.h>

// Problem constants (fixed shapes)
#define M_NODES   131072
#define K_DIM     256
#define N_PROJ    256
#define NUM_G     256
#define NPG       512          // nodes per graph
#define NUM_Q     256

#define NW        152          // persistent workers per role (GB300: 152 SMs)
#define NTILES    (M_NODES / 64)       // 2048 gemm tiles
#define NUNITS    ((NUM_G * N_PROJ) / 8)  // 8192 sort units (8 cols each)

// Scratch (device globals; no allocation allowed in kernel_launch)
__device__ __nv_bfloat16 g_bhi[N_PROJ * K_DIM];            // proj^T hi [n][k]
__device__ __nv_bfloat16 g_blo[N_PROJ * K_DIM];            // proj^T lo [n][k]
__device__ float g_xpt[(size_t)NUM_G * N_PROJ * NPG];      // xp transposed [g][p][i]
__device__ int   g_cnt[NUM_G];                             // per-graph gemm arrivals

// ---------------------------------------------------------------------------
// PTX helpers (base ISA only — no sm_103a-gated features)
// ---------------------------------------------------------------------------
__device__ __forceinline__ uint32_t smem_u32(const void* p) {
    uint32_t a;
    asm("{ .reg .u64 t; cvta.to.shared.u64 t, %1; cvt.u32.u64 %0, t; }" : "=r"(a) : "l"(p));
    return a;
}
__device__ __forceinline__ void cp_async16(uint32_t saddr, const void* gptr) {
    asm volatile("cp.async.cg.shared.global [%0], [%1], 16;" :: "r"(saddr), "l"(gptr));
}
__device__ __forceinline__ void cp_commit() { asm volatile("cp.async.commit_group;"); }
__device__ __forceinline__ void cp_wait1()  { asm volatile("cp.async.wait_group 1;"); }
__device__ __forceinline__ void cp_wait0()  { asm volatile("cp.async.wait_group 0;"); }

__device__ __forceinline__ void ldsm4(uint32_t& r0, uint32_t& r1, uint32_t& r2, uint32_t& r3,
                                      uint32_t addr) {
    asm volatile("ldmatrix.sync.aligned.m8n8.x4.shared.b16 {%0,%1,%2,%3}, [%4];"
                 : "=r"(r0), "=r"(r1), "=r"(r2), "=r"(r3) : "r"(addr));
}
__device__ __forceinline__ void mma_bf16(float* c, const uint32_t* a, uint32_t b0, uint32_t b1) {
    asm volatile("mma.sync.aligned.m16n8k16.row.col.f32.bf16.bf16.f32 "
                 "{%0,%1,%2,%3}, {%4,%5,%6,%7}, {%8,%9}, {%0,%1,%2,%3};"
                 : "+f"(c[0]), "+f"(c[1]), "+f"(c[2]), "+f"(c[3])
                 : "r"(a[0]), "r"(a[1]), "r"(a[2]), "r"(a[3]), "r"(b0), "r"(b1));
}
__device__ __forceinline__ uint32_t pkbf(float a, float b) {
    __nv_bfloat16 h0 = __float2bfloat16(a);
    __nv_bfloat16 h1 = __float2bfloat16(b);
    return (uint32_t)__bfloat16_as_ushort(h0) | ((uint32_t)__bfloat16_as_ushort(h1) << 16);
}

// ---------------------------------------------------------------------------
// Kernel 1: split-convert + transpose proj; block 0 also resets g_cnt.
// ---------------------------------------------------------------------------
__global__ void convp_kernel(const float* __restrict__ proj) {
    int n = blockIdx.x, k = threadIdx.x;
    if (n == 0) g_cnt[k] = 0;
    float v = proj[(size_t)k * N_PROJ + n];
    __nv_bfloat16 h = __float2bfloat16(v);
    __nv_bfloat16 l = __float2bfloat16(v - __bfloat162float(h));
    g_bhi[n * K_DIM + k] = h;
    g_blo[n * K_DIM + k] = l;
}

// ---------------------------------------------------------------------------
// Sort building blocks: per-warp bitonic sort of 512 values
// ---------------------------------------------------------------------------
template<int KK, int J>
__device__ __forceinline__ void bstep(float (&v)[16], int lane) {
    if constexpr (J >= 16) {
#pragma unroll
        for (int r = 0; r < 16; r++) {
            float pv = __shfl_xor_sync(0xffffffffu, v[r], J >> 4);
            int i = lane * 16 + r;
            bool takeMin = ((i & KK) == 0) == ((i & J) == 0);
            v[r] = takeMin ? fminf(v[r], pv) : fmaxf(v[r], pv);
        }
    } else {
#pragma unroll
        for (int r = 0; r < 16; r++) {
            if ((r & J) == 0) {
                int i = lane * 16 + r;
                bool up = ((i & KK) == 0);
                float a = v[r], b = v[r | J];
                float mn = fminf(a, b), mx = fmaxf(a, b);
                v[r]     = up ? mn : mx;
                v[r | J] = up ? mx : mn;
            }
        }
    }
}
template<int KK, int J>
__device__ __forceinline__ void bmerge(float (&v)[16], int lane) {
    bstep<KK, J>(v, lane);
    if constexpr (J > 1) bmerge<KK, J / 2>(v, lane);
}

// ---------------------------------------------------------------------------
// Fused persistent kernel, CTA-role specialized:
//   bid <  NW : GEMM worker — loops over tiles (BM=64 x BN=256 bf16-split HMMA),
//               writes g_xpt, signals g_cnt[graph] per tile.
//   bid >= NW : sort worker — loops over 8-column units, spin-waits for the
//               unit's graph (8 tiles), sorts + emits quantiles.
//   With 2 CTAs/SM, wave 1 = gemm on every SM, wave 2 = sort on every SM:
//   tensor-pipe and alu-pipe work overlap continuously.
// ---------------------------------------------------------------------------
#define BM 64
#define BN 256
#define BK 32
#define GTHREADS 256
#define S_BOP   16384    // bOp[2]: 256 rows x 128B = 32768 each
#define FUSED_SMEM 81920
#define EPAD 68          // epilogue staging stride (floats)

__global__ void __launch_bounds__(GTHREADS, 2)
fused_kernel(const float* __restrict__ x, const float* __restrict__ cw,
             float* __restrict__ out) {
    extern __shared__ char smem[];
    const uint32_t sb = smem_u32(smem);

    const int t    = threadIdx.x;
    const int lane = t & 31;
    const int wid  = t >> 5;
    const int b    = blockIdx.x;

    if (b < NW) {
        // ==================== GEMM worker ====================
        const int wm = (wid >> 2) * 32;   // warp tile 32 x 64
        const int wn = (wid & 3) * 64;

        const int rsel  = lane & 15;
        const int khalf = lane >> 4;
        const int kx    = lane & 7;

        uint32_t mByte[2], nByte[4];
#pragma unroll
        for (int mi = 0; mi < 2; mi++) mByte[mi] = (uint32_t)(wm + mi * 16 + rsel) * 128;
#pragma unroll
        for (int ni = 0; ni < 4; ni++) nByte[ni] = (uint32_t)(wn + ni * 16 + rsel) * 128;

        const int arow = t >> 2;
        const int aq   = t & 3;
        const uint32_t swH = (uint32_t)(arow * 128 + ((aq)     ^ (arow & 7)) * 16);
        const uint32_t swL = (uint32_t)(arow * 128 + ((aq + 4) ^ (arow & 7)) * 16);

        for (int tb = b; tb < NTILES; tb += NW) {
            const int mBase = tb * BM;
            const int gId   = tb >> 3;
            const float* aSrc = x + (size_t)(mBase + arow) * K_DIM + aq * 8;

            float aF[8];
            auto ldgA = [&](int c) {
                const float4* p = (const float4*)(aSrc + c * BK);
                float4 u0 = p[0], u1 = p[1];
                aF[0] = u0.x; aF[1] = u0.y; aF[2] = u0.z; aF[3] = u0.w;
                aF[4] = u1.x; aF[5] = u1.y; aF[6] = u1.z; aF[7] = u1.w;
            };
            auto stsA = [&](int buf) {
                uint32_t h[4], l[4];
#pragma unroll
                for (int j = 0; j < 4; j++) {
                    float f0 = aF[2 * j], f1 = aF[2 * j + 1];
                    h[j] = pkbf(f0, f1);
                    float r0 = f0 - __bfloat162float(__ushort_as_bfloat16((uint16_t)h[j]));
                    float r1 = f1 - __bfloat162float(__ushort_as_bfloat16((uint16_t)(h[j] >> 16)));
                    l[j] = pkbf(r0, r1);
                }
                char* base = smem + buf * 8192;
                *(uint4*)(base + swH) = make_uint4(h[0], h[1], h[2], h[3]);
                *(uint4*)(base + swL) = make_uint4(l[0], l[1], l[2], l[3]);
            };
            auto cpB = [&](int c) {
                const int kB = c * BK;
                const uint32_t bufB = sb + S_BOP + (c & 1) * 32768;
#pragma unroll
                for (int r = 0; r < 8; r++) {
                    int u   = t + GTHREADS * r;          // 0..2047
                    int row = u >> 3;
                    int gg  = u & 7;                     // 0..3 hi, 4..7 lo
                    uint32_t off = (uint32_t)(row * 128 + gg * 16);
                    uint32_t sw  = off ^ ((off >> 3) & 0x70);
                    const __nv_bfloat16* bsrc = (gg < 4 ? g_bhi : g_blo)
                                              + (size_t)row * K_DIM + kB + (gg & 3) * 8;
                    cp_async16(bufB + sw, bsrc);
                }
                cp_commit();
            };

            float acc[2][8][4];
#pragma unroll
            for (int mi = 0; mi < 2; mi++)
#pragma unroll
                for (int ni = 0; ni < 8; ni++)
#pragma unroll
                    for (int r = 0; r < 4; r++) acc[mi][ni][r] = 0.0f;

            ldgA(0);
            cpB(0);
            cpB(1);
            stsA(0);
            ldgA(1);

            const int NCH = K_DIM / BK;   // 8
            for (int c = 0; c < NCH; c++) {
                if (c < NCH - 1) cp_wait1(); else cp_wait0();
                __syncthreads();

                if (c + 1 < NCH) stsA((c + 1) & 1);
                if (c + 2 < NCH) ldgA(c + 2);

                const uint32_t bufA = sb + (c & 1) * 8192;
                const uint32_t bufB = sb + S_BOP + (c & 1) * 32768;

#pragma unroll
                for (int ks = 0; ks < 2; ks++) {
                    const uint32_t segH = (uint32_t)((ks * 2 + khalf) ^ kx) << 4;
                    const uint32_t segL = (uint32_t)((4 + ks * 2 + khalf) ^ kx) << 4;

                    uint32_t ah[2][4], bh[4][4];
#pragma unroll
                    for (int mi = 0; mi < 2; mi++)
                        ldsm4(ah[mi][0], ah[mi][1], ah[mi][2], ah[mi][3], bufA + mByte[mi] + segH);
#pragma unroll
                    for (int ni = 0; ni < 4; ni++)
                        ldsm4(bh[ni][0], bh[ni][1], bh[ni][2], bh[ni][3], bufB + nByte[ni] + segH);

                    // pass 1: Ah * Bh
#pragma unroll
                    for (int mi = 0; mi < 2; mi++)
#pragma unroll
                        for (int ni = 0; ni < 8; ni++)
                            mma_bf16(acc[mi][ni], ah[mi], bh[ni >> 1][ni & 1], bh[ni >> 1][(ni & 1) + 2]);

                    // pass 2: Ah * Bl
                    uint32_t bl[4][4];
#pragma unroll
                    for (int ni = 0; ni < 4; ni++)
                        ldsm4(bl[ni][0], bl[ni][1], bl[ni][2], bl[ni][3], bufB + nByte[ni] + segL);
#pragma unroll
                    for (int mi = 0; mi < 2; mi++)
#pragma unroll
                        for (int ni = 0; ni < 8; ni++)
                            mma_bf16(acc[mi][ni], ah[mi], bl[ni >> 1][ni & 1], bl[ni >> 1][(ni & 1) + 2]);

                    // pass 3: Al * Bh
                    uint32_t al[2][4];
#pragma unroll
                    for (int mi = 0; mi < 2; mi++)
                        ldsm4(al[mi][0], al[mi][1], al[mi][2], al[mi][3], bufA + mByte[mi] + segL);
#pragma unroll
                    for (int mi = 0; mi < 2; mi++)
#pragma unroll
                        for (int ni = 0; ni < 8; ni++)
                            mma_bf16(acc[mi][ni], al[mi], bh[ni >> 1][ni & 1], bh[ni >> 1][(ni & 1) + 2]);
                }

                __syncthreads();
                if (c + 2 < NCH) cpB(c + 2);
            }

            // Epilogue: stage D transposed in smem [n][m], then coalesced STG
            float* sOut = (float*)smem;
            const int crow = lane >> 2;
            const int ccol = (lane & 3) * 2;
#pragma unroll
            for (int mi = 0; mi < 2; mi++)
#pragma unroll
                for (int ni = 0; ni < 8; ni++) {
                    int m0 = wm + mi * 16 + crow;
                    int n0 = wn + ni * 8 + ccol;
                    sOut[(n0    ) * EPAD + m0    ] = acc[mi][ni][0];
                    sOut[(n0 + 1) * EPAD + m0    ] = acc[mi][ni][1];
                    sOut[(n0    ) * EPAD + m0 + 8] = acc[mi][ni][2];
                    sOut[(n0 + 1) * EPAD + m0 + 8] = acc[mi][ni][3];
                }
            __syncthreads();

            const int iBase = mBase & 511;
#pragma unroll
            for (int r = 0; r < 16; r++) {
                int u   = t + GTHREADS * r;          // 0..4095
                int row = u >> 4;                    // n 0..255
                int pos = u & 15;                    // float4 within 64 m
                float4 v4 = *(float4*)&sOut[row * EPAD + pos * 4];
                float* dst = g_xpt + ((size_t)(gId * N_PROJ + row)) * NPG + iBase + pos * 4;
                *(float4*)dst = v4;
            }

            // Signal: this tile of graph gId is globally visible
            __syncthreads();
            __threadfence();
            if (t == 0) atomicAdd(&g_cnt[gId], 1);
            __syncthreads();   // protect smem reuse by next tile
        }
    } else {
        // ==================== sort worker ====================
        const int s = b - NW;
        float* sbuf = (float*)smem;                        // [8][512]
        float* qbuf = (float*)(smem + 16384);              // [8][264]
        int*   qidx = (int*)(smem + 16384 + 8 * 264 * 4);  // [256]

        qidx[t] = (int)floorf(cw[t] * (float)(NPG - 1));   // matches jnp.floor(cw*511)

        for (int u = s; u < NUNITS; u += NW) {
            const int gId = u >> 5;                        // graph of this unit

            if (t == 0) {
                while (atomicAdd(&g_cnt[gId], 0) < 8) __nanosleep(128);
                __threadfence();
            }
            __syncthreads();

            const int col = u * 8 + wid;                   // (g,p) column id

            float v[16];
            const float4* src = (const float4*)(g_xpt + (size_t)col * NPG);
#pragma unroll
            for (int q = 0; q < 4; q++) {
                float4 f = src[lane * 4 + q];
                v[q * 4 + 0] = f.x; v[q * 4 + 1] = f.y;
                v[q * 4 + 2] = f.z; v[q * 4 + 3] = f.w;
            }

            bmerge<2, 1>(v, lane);
            bmerge<4, 2>(v, lane);
            bmerge<8, 4>(v, lane);
            bmerge<16, 8>(v, lane);
            bmerge<32, 16>(v, lane);
            bmerge<64, 32>(v, lane);
            bmerge<128, 64>(v, lane);
            bmerge<256, 128>(v, lane);
            bmerge<512, 256>(v, lane);

            float4* dst = (float4*)(sbuf + wid * 512);
#pragma unroll
            for (int q = 0; q < 4; q++)
                dst[lane * 4 + q] = make_float4(v[q * 4 + 0], v[q * 4 + 1],
                                                v[q * 4 + 2], v[q * 4 + 3]);
            __syncwarp();

#pragma unroll
            for (int sq = 0; sq < 8; sq++) {
                int q = lane + 32 * sq;
                qbuf[wid * 264 + q] = sbuf[wid * 512 + qidx[q]] * (1.0f / 256.0f);
            }
            __syncthreads();

            // Coalesced write: out[g*65536 + q*256 + p], 8 consecutive p
            const int pbase = (u * 8) & 255;
            const size_t obase = (size_t)gId * (NUM_Q * N_PROJ) + pbase;
#pragma unroll
            for (int sq = 0; sq < 8; sq++) {
                int e  = t + 256 * sq;          // 0..2047
                int q  = e >> 3;
                int wp = e & 7;
                out[obase + (size_t)q * N_PROJ + wp] = qbuf[wp * 264 + q];
            }
            __syncthreads();
        }
    }
}

// ---------------------------------------------------------------------------
// kernel_launch: convp (+counter reset) -> persistent fused kernel
// ---------------------------------------------------------------------------
extern "C" void kernel_launch(void* const* d_in, const int* in_sizes, int n_in,
                              void* d_out, int out_size) {
    const float* x    = (const float*)d_in[0];   // [131072, 256] f32
    const float* proj = (const float*)d_in[1];   // [256, 256]    f32
    const float* cw   = (const float*)d_in[2];   // [256]         f32
    float* out = (float*)d_out;                  // [256, 65536]  f32

    cudaFuncSetAttribute(fused_kernel,
                         cudaFuncAttributeMaxDynamicSharedMemorySize,
                         FUSED_SMEM);

    convp_kernel<<<N_PROJ, K_DIM>>>(proj);
    fused_kernel<<<2 * NW, GTHREADS, FUSED_SMEM>>>(x, cw, out);
}

// round 13
// speedup vs baseline: 1.5347x; 1.5347x over previous
#include <cuda_runtime.h>
#include <cuda_bf16.h>
#include <stdint.h>

// Problem constants (fixed shapes)
#define M_NODES   131072
#define K_DIM     256
#define N_PROJ    256
#define NUM_G     256
#define NPG       512          // nodes per graph
#define NUM_Q     256

// Scratch (device globals; no allocation allowed in kernel_launch)
__device__ __nv_bfloat16 g_bhi[N_PROJ * K_DIM];            // proj^T hi [n][k]
__device__ __nv_bfloat16 g_blo[N_PROJ * K_DIM];            // proj^T lo [n][k]
__device__ float g_xpt[(size_t)NUM_G * N_PROJ * NPG];      // xp transposed [g][p][i]

// ---------------------------------------------------------------------------
// PTX helpers (base ISA only — no sm_103a-gated features)
// ---------------------------------------------------------------------------
__device__ __forceinline__ uint32_t smem_u32(const void* p) {
    uint32_t a;
    asm("{ .reg .u64 t; cvta.to.shared.u64 t, %1; cvt.u32.u64 %0, t; }" : "=r"(a) : "l"(p));
    return a;
}
__device__ __forceinline__ void cp_async16(uint32_t saddr, const void* gptr) {
    asm volatile("cp.async.cg.shared.global [%0], [%1], 16;" :: "r"(saddr), "l"(gptr));
}
__device__ __forceinline__ void cp_commit() { asm volatile("cp.async.commit_group;"); }
__device__ __forceinline__ void cp_wait1()  { asm volatile("cp.async.wait_group 1;"); }
__device__ __forceinline__ void cp_wait0()  { asm volatile("cp.async.wait_group 0;"); }

__device__ __forceinline__ void ldsm4(uint32_t& r0, uint32_t& r1, uint32_t& r2, uint32_t& r3,
                                      uint32_t addr) {
    asm volatile("ldmatrix.sync.aligned.m8n8.x4.shared.b16 {%0,%1,%2,%3}, [%4];"
                 : "=r"(r0), "=r"(r1), "=r"(r2), "=r"(r3) : "r"(addr));
}
__device__ __forceinline__ void mma_bf16(float* c, const uint32_t* a, uint32_t b0, uint32_t b1) {
    asm volatile("mma.sync.aligned.m16n8k16.row.col.f32.bf16.bf16.f32 "
                 "{%0,%1,%2,%3}, {%4,%5,%6,%7}, {%8,%9}, {%0,%1,%2,%3};"
                 : "+f"(c[0]), "+f"(c[1]), "+f"(c[2]), "+f"(c[3])
                 : "r"(a[0]), "r"(a[1]), "r"(a[2]), "r"(a[3]), "r"(b0), "r"(b1));
}
__device__ __forceinline__ uint32_t pkbf(float a, float b) {
    __nv_bfloat16 h0 = __float2bfloat16(a);
    __nv_bfloat16 h1 = __float2bfloat16(b);
    return (uint32_t)__bfloat16_as_ushort(h0) | ((uint32_t)__bfloat16_as_ushort(h1) << 16);
}

// ---------------------------------------------------------------------------
// Kernel 1: split-convert + transpose proj -> B[n][k] (K-major); tiny.
// ---------------------------------------------------------------------------
__global__ void convp_kernel(const float* __restrict__ proj) {
    int n = blockIdx.x, k = threadIdx.x;
    float v = proj[(size_t)k * N_PROJ + n];
    __nv_bfloat16 h = __float2bfloat16(v);
    __nv_bfloat16 l = __float2bfloat16(v - __bfloat162float(h));
    g_bhi[n * K_DIM + k] = h;
    g_blo[n * K_DIM + k] = l;
}

// ---------------------------------------------------------------------------
// Kernel 2: fused HMMA bf16-split GEMM, BM=64 BN=256 BK=32.
//   A: fp32 x loaded via LDG, split to bf16 hi/lo in-kernel, STS to SW128 smem.
//   B: pre-split bf16 via cp.async (L2-resident).
//   3 passes per K-chunk: Ah*Bh + Ah*Bl + Al*Bh, fp32 accum.
//   Epilogue writes transposed into g_xpt[g][p][i] (smem-staged, coalesced).
// ---------------------------------------------------------------------------
#define BM 64
#define BN 256
#define BK 32
#define GTHREADS 256
#define S_BOP   16384    // bOp[2]: 256 rows x 128B = 32768 each
#define GEMM_SMEM 81920
#define EPAD 68          // epilogue staging stride (floats)

__global__ void __launch_bounds__(GTHREADS, 2)
gemm_hmma_kernel(const float* __restrict__ x) {
    extern __shared__ char smem[];
    const uint32_t sb = smem_u32(smem);

    const int t     = threadIdx.x;
    const int lane  = t & 31;
    const int wid   = t >> 5;
    const int mBase = blockIdx.x * BM;
    const int wm    = (wid >> 2) * 32;   // warp tile 32 x 64
    const int wn    = (wid & 3) * 64;

    const int rsel  = lane & 15;
    const int khalf = lane >> 4;
    const int kx    = lane & 7;

    uint32_t mByte[2], nByte[4];
#pragma unroll
    for (int mi = 0; mi < 2; mi++) mByte[mi] = (uint32_t)(wm + mi * 16 + rsel) * 128;
#pragma unroll
    for (int ni = 0; ni < 4; ni++) nByte[ni] = (uint32_t)(wn + ni * 16 + rsel) * 128;

    const int arow = t >> 2;
    const int aq   = t & 3;
    const float* aSrc = x + (size_t)(mBase + arow) * K_DIM + aq * 8;
    const uint32_t swH = (uint32_t)(arow * 128 + ((aq)     ^ (arow & 7)) * 16);
    const uint32_t swL = (uint32_t)(arow * 128 + ((aq + 4) ^ (arow & 7)) * 16);

    float aF[8];
    auto ldgA = [&](int c) {
        const float4* p = (const float4*)(aSrc + c * BK);
        float4 u0 = p[0], u1 = p[1];
        aF[0] = u0.x; aF[1] = u0.y; aF[2] = u0.z; aF[3] = u0.w;
        aF[4] = u1.x; aF[5] = u1.y; aF[6] = u1.z; aF[7] = u1.w;
    };
    auto stsA = [&](int buf) {
        uint32_t h[4], l[4];
#pragma unroll
        for (int j = 0; j < 4; j++) {
            float f0 = aF[2 * j], f1 = aF[2 * j + 1];
            h[j] = pkbf(f0, f1);
            float r0 = f0 - __bfloat162float(__ushort_as_bfloat16((uint16_t)h[j]));
            float r1 = f1 - __bfloat162float(__ushort_as_bfloat16((uint16_t)(h[j] >> 16)));
            l[j] = pkbf(r0, r1);
        }
        char* base = smem + buf * 8192;
        *(uint4*)(base + swH) = make_uint4(h[0], h[1], h[2], h[3]);
        *(uint4*)(base + swL) = make_uint4(l[0], l[1], l[2], l[3]);
    };
    auto cpB = [&](int c) {
        const int kB = c * BK;
        const uint32_t bufB = sb + S_BOP + (c & 1) * 32768;
#pragma unroll
        for (int r = 0; r < 8; r++) {
            int u   = t + GTHREADS * r;          // 0..2047
            int row = u >> 3;
            int gg  = u & 7;                     // 0..3 hi, 4..7 lo
            uint32_t off = (uint32_t)(row * 128 + gg * 16);
            uint32_t sw  = off ^ ((off >> 3) & 0x70);
            const __nv_bfloat16* bsrc = (gg < 4 ? g_bhi : g_blo)
                                      + (size_t)row * K_DIM + kB + (gg & 3) * 8;
            cp_async16(bufB + sw, bsrc);
        }
        cp_commit();
    };

    float acc[2][8][4];
#pragma unroll
    for (int mi = 0; mi < 2; mi++)
#pragma unroll
        for (int ni = 0; ni < 8; ni++)
#pragma unroll
            for (int r = 0; r < 4; r++) acc[mi][ni][r] = 0.0f;

    ldgA(0);
    cpB(0);
    cpB(1);
    stsA(0);
    ldgA(1);

    const int NCH = K_DIM / BK;   // 8
    for (int c = 0; c < NCH; c++) {
        if (c < NCH - 1) cp_wait1(); else cp_wait0();
        __syncthreads();

        if (c + 1 < NCH) stsA((c + 1) & 1);
        if (c + 2 < NCH) ldgA(c + 2);

        const uint32_t bufA = sb + (c & 1) * 8192;
        const uint32_t bufB = sb + S_BOP + (c & 1) * 32768;

#pragma unroll
        for (int ks = 0; ks < 2; ks++) {
            const uint32_t segH = (uint32_t)((ks * 2 + khalf) ^ kx) << 4;
            const uint32_t segL = (uint32_t)((4 + ks * 2 + khalf) ^ kx) << 4;

            uint32_t ah[2][4], bh[4][4];
#pragma unroll
            for (int mi = 0; mi < 2; mi++)
                ldsm4(ah[mi][0], ah[mi][1], ah[mi][2], ah[mi][3], bufA + mByte[mi] + segH);
#pragma unroll
            for (int ni = 0; ni < 4; ni++)
                ldsm4(bh[ni][0], bh[ni][1], bh[ni][2], bh[ni][3], bufB + nByte[ni] + segH);

            // pass 1: Ah * Bh
#pragma unroll
            for (int mi = 0; mi < 2; mi++)
#pragma unroll
                for (int ni = 0; ni < 8; ni++)
                    mma_bf16(acc[mi][ni], ah[mi], bh[ni >> 1][ni & 1], bh[ni >> 1][(ni & 1) + 2]);

            // pass 2: Ah * Bl
            uint32_t bl[4][4];
#pragma unroll
            for (int ni = 0; ni < 4; ni++)
                ldsm4(bl[ni][0], bl[ni][1], bl[ni][2], bl[ni][3], bufB + nByte[ni] + segL);
#pragma unroll
            for (int mi = 0; mi < 2; mi++)
#pragma unroll
                for (int ni = 0; ni < 8; ni++)
                    mma_bf16(acc[mi][ni], ah[mi], bl[ni >> 1][ni & 1], bl[ni >> 1][(ni & 1) + 2]);

            // pass 3: Al * Bh
            uint32_t al[2][4];
#pragma unroll
            for (int mi = 0; mi < 2; mi++)
                ldsm4(al[mi][0], al[mi][1], al[mi][2], al[mi][3], bufA + mByte[mi] + segL);
#pragma unroll
            for (int mi = 0; mi < 2; mi++)
#pragma unroll
                for (int ni = 0; ni < 8; ni++)
                    mma_bf16(acc[mi][ni], al[mi], bh[ni >> 1][ni & 1], bh[ni >> 1][(ni & 1) + 2]);
        }

        __syncthreads();
        if (c + 2 < NCH) cpB(c + 2);
    }

    // Epilogue: stage D transposed in smem [n][m] (stride EPAD -> conflict-free)
    float* sOut = (float*)smem;
    const int crow = lane >> 2;
    const int ccol = (lane & 3) * 2;
#pragma unroll
    for (int mi = 0; mi < 2; mi++)
#pragma unroll
        for (int ni = 0; ni < 8; ni++) {
            int m0 = wm + mi * 16 + crow;
            int n0 = wn + ni * 8 + ccol;
            sOut[(n0    ) * EPAD + m0    ] = acc[mi][ni][0];
            sOut[(n0 + 1) * EPAD + m0    ] = acc[mi][ni][1];
            sOut[(n0    ) * EPAD + m0 + 8] = acc[mi][ni][2];
            sOut[(n0 + 1) * EPAD + m0 + 8] = acc[mi][ni][3];
        }
    __syncthreads();

    // Coalesced global write: g_xpt[(g*256 + n)*512 + i]
    const int g     = mBase >> 9;
    const int iBase = mBase & 511;
#pragma unroll
    for (int r = 0; r < 16; r++) {
        int u   = t + GTHREADS * r;          // 0..4095
        int row = u >> 4;                    // n 0..255
        int pos = u & 15;                    // float4 within 64 m
        float4 v = *(float4*)&sOut[row * EPAD + pos * 4];
        float* dst = g_xpt + ((size_t)(g * N_PROJ + row)) * NPG + iBase + pos * 4;
        *(float4*)dst = v;
    }
}

// ---------------------------------------------------------------------------
// Kernel 3: per-warp bitonic sort of 512 values + quantile gather + write.
//   In-register exchanges use the alu/fma split:
//     c0 = (up ? min : max)(a,b)   -> 1 FMNMX (alu pipe, predicate-selected)
//     other = (a+b) - c0           -> 2 FFMA-imm (fma pipe, rt=1)
//   halving alu-pipe traffic vs min+max pairs.
// ---------------------------------------------------------------------------
template<int KK, int J>
__device__ __forceinline__ void bstep(float (&v)[16], int lane) {
    if constexpr (J >= 16) {
#pragma unroll
        for (int r = 0; r < 16; r++) {
            float pv = __shfl_xor_sync(0xffffffffu, v[r], J >> 4);
            int i = lane * 16 + r;
            bool takeMin = ((i & KK) == 0) == ((i & J) == 0);
            v[r] = takeMin ? fminf(v[r], pv) : fmaxf(v[r], pv);
        }
    } else {
#pragma unroll
        for (int r = 0; r < 16; r++) {
            if ((r & J) == 0) {
                int i = lane * 16 + r;
                bool up = ((i & KK) == 0);
                float a = v[r], b = v[r | J];
                float s  = __fmaf_rn(a, 1.0f, b);          // fma pipe
                float c0 = up ? fminf(a, b) : fmaxf(a, b); // 1 FMNMX (alu)
                v[r]     = c0;
                v[r | J] = __fmaf_rn(c0, -1.0f, s);        // fma pipe
            }
        }
    }
}
template<int KK, int J>
__device__ __forceinline__ void bmerge(float (&v)[16], int lane) {
    bstep<KK, J>(v, lane);
    if constexpr (J > 1) bmerge<KK, J / 2>(v, lane);
}

__global__ void __launch_bounds__(256)
sort_quant_kernel(const float* __restrict__ cw, float* __restrict__ out) {
    __shared__ float sbuf[8][512];      // sorted columns, one per warp
    __shared__ float qbuf[8][264];      // quantiles staged (padded stride)
    __shared__ int   qidx[NUM_Q];

    const int t = threadIdx.x;
    qidx[t] = (int)floorf(cw[t] * (float)(NPG - 1));   // matches jnp.floor(cw*511)
    __syncthreads();

    const int w    = t >> 5;
    const int lane = t & 31;
    const int col  = blockIdx.x * 8 + w;               // (g,p) column id

    float v[16];
    const float4* src = (const float4*)(g_xpt + (size_t)col * NPG);
#pragma unroll
    for (int q = 0; q < 4; q++) {
        float4 f = src[lane * 4 + q];
        v[q * 4 + 0] = f.x; v[q * 4 + 1] = f.y;
        v[q * 4 + 2] = f.z; v[q * 4 + 3] = f.w;
    }

    bmerge<2, 1>(v, lane);
    bmerge<4, 2>(v, lane);
    bmerge<8, 4>(v, lane);
    bmerge<16, 8>(v, lane);
    bmerge<32, 16>(v, lane);
    bmerge<64, 32>(v, lane);
    bmerge<128, 64>(v, lane);
    bmerge<256, 128>(v, lane);
    bmerge<512, 256>(v, lane);

    float4* dst = (float4*)sbuf[w];
#pragma unroll
    for (int q = 0; q < 4; q++)
        dst[lane * 4 + q] = make_float4(v[q * 4 + 0], v[q * 4 + 1], v[q * 4 + 2], v[q * 4 + 3]);
    __syncwarp();

#pragma unroll
    for (int s = 0; s < 8; s++) {
        int q = lane + 32 * s;
        qbuf[w][q] = sbuf[w][qidx[q]] * (1.0f / 256.0f);
    }
    __syncthreads();

    const int gg    = blockIdx.x >> 5;
    const int pbase = (blockIdx.x * 8) & 255;
    const size_t obase = (size_t)gg * (NUM_Q * N_PROJ) + pbase;
#pragma unroll
    for (int s = 0; s < 8; s++) {
        int e  = t + 256 * s;          // 0..2047
        int q  = e >> 3;
        int wp = e & 7;
        out[obase + (size_t)q * N_PROJ + wp] = qbuf[wp][q];
    }
}

// ---------------------------------------------------------------------------
// kernel_launch: convp -> HMMA gemm -> sort/quantile (graph-capturable)
// ---------------------------------------------------------------------------
extern "C" void kernel_launch(void* const* d_in, const int* in_sizes, int n_in,
                              void* d_out, int out_size) {
    const float* x    = (const float*)d_in[0];   // [131072, 256] f32
    const float* proj = (const float*)d_in[1];   // [256, 256]    f32
    const float* cw   = (const float*)d_in[2];   // [256]         f32
    float* out = (float*)d_out;                  // [256, 65536]  f32

    cudaFuncSetAttribute(gemm_hmma_kernel,
                         cudaFuncAttributeMaxDynamicSharedMemorySize,
                         GEMM_SMEM);

    convp_kernel<<<N_PROJ, K_DIM>>>(proj);
    gemm_hmma_kernel<<<M_NODES / BM, GTHREADS, GEMM_SMEM>>>(x);
    sort_quant_kernel<<<(NUM_G * N_PROJ) / 8, 256>>>(cw, out);
}

// round 14
// speedup vs baseline: 2.1587x; 1.4066x over previous
#include <cuda_runtime.h>
#include <cuda_fp16.h>
#include <stdint.h>

// Problem constants (fixed shapes)
#define M_NODES   131072
#define K_DIM     256
#define N_PROJ    256
#define NUM_G     256
#define NPG       512          // nodes per graph
#define NUM_Q     256

// Scratch (device globals; no allocation allowed in kernel_launch)
__device__ __half g_bh[N_PROJ * K_DIM];                    // proj^T fp16 [n][k]
__device__ float g_xpt[(size_t)NUM_G * N_PROJ * NPG];      // xp transposed [g][p][i]

// ---------------------------------------------------------------------------
// PTX helpers (base ISA only — no sm_103a-gated features)
// ---------------------------------------------------------------------------
__device__ __forceinline__ uint32_t smem_u32(const void* p) {
    uint32_t a;
    asm("{ .reg .u64 t; cvta.to.shared.u64 t, %1; cvt.u32.u64 %0, t; }" : "=r"(a) : "l"(p));
    return a;
}
__device__ __forceinline__ void cp_async16(uint32_t saddr, const void* gptr) {
    asm volatile("cp.async.cg.shared.global [%0], [%1], 16;" :: "r"(saddr), "l"(gptr));
}
__device__ __forceinline__ void cp_commit() { asm volatile("cp.async.commit_group;"); }
__device__ __forceinline__ void cp_wait1()  { asm volatile("cp.async.wait_group 1;"); }
__device__ __forceinline__ void cp_wait0()  { asm volatile("cp.async.wait_group 0;"); }

__device__ __forceinline__ void ldsm4(uint32_t& r0, uint32_t& r1, uint32_t& r2, uint32_t& r3,
                                      uint32_t addr) {
    asm volatile("ldmatrix.sync.aligned.m8n8.x4.shared.b16 {%0,%1,%2,%3}, [%4];"
                 : "=r"(r0), "=r"(r1), "=r"(r2), "=r"(r3) : "r"(addr));
}
__device__ __forceinline__ void mma_fp16(float* c, const uint32_t* a, uint32_t b0, uint32_t b1) {
    asm volatile("mma.sync.aligned.m16n8k16.row.col.f32.f16.f16.f32 "
                 "{%0,%1,%2,%3}, {%4,%5,%6,%7}, {%8,%9}, {%0,%1,%2,%3};"
                 : "+f"(c[0]), "+f"(c[1]), "+f"(c[2]), "+f"(c[3])
                 : "r"(a[0]), "r"(a[1]), "r"(a[2]), "r"(a[3]), "r"(b0), "r"(b1));
}

// ---------------------------------------------------------------------------
// Kernel 1: convert + transpose proj -> B[n][k] fp16 (K-major); tiny.
// ---------------------------------------------------------------------------
__global__ void convp_kernel(const float* __restrict__ proj) {
    int n = blockIdx.x, k = threadIdx.x;
    g_bh[n * K_DIM + k] = __float2half_rn(proj[(size_t)k * N_PROJ + n]);
}

// ---------------------------------------------------------------------------
// Kernel 2: single-pass fp16 HMMA GEMM, BM=64 BN=256 BK=64.
//   A: fp32 x via LDG, converted to fp16 in-flight, STS to SW128 smem.
//   B: fp16 via cp.async (L2-resident).
//   Epilogue writes transposed into g_xpt[g][p][i] (smem-staged, coalesced).
// ---------------------------------------------------------------------------
#define BM 64
#define BN 256
#define BK 64
#define GTHREADS 256
#define S_BOP   16384    // bOp[2]: 256 rows x 128B = 32768 each
#define GEMM_SMEM 81920
#define EPAD 68          // epilogue staging stride (floats)

__global__ void __launch_bounds__(GTHREADS, 2)
gemm_hmma_kernel(const float* __restrict__ x) {
    extern __shared__ char smem[];
    const uint32_t sb = smem_u32(smem);

    const int t     = threadIdx.x;
    const int lane  = t & 31;
    const int wid   = t >> 5;
    const int mBase = blockIdx.x * BM;
    const int wm    = (wid >> 2) * 32;   // warp tile 32 x 64
    const int wn    = (wid & 3) * 64;

    const int rsel  = lane & 15;
    const int khalf = lane >> 4;
    const int kx    = lane & 7;

    uint32_t mByte[2], nByte[4];
#pragma unroll
    for (int mi = 0; mi < 2; mi++) mByte[mi] = (uint32_t)(wm + mi * 16 + rsel) * 128;
#pragma unroll
    for (int ni = 0; ni < 4; ni++) nByte[ni] = (uint32_t)(wn + ni * 16 + rsel) * 128;

    // A staging: 512 granules (64 rows x 8 x 16B); 2 granules per thread.
    int aRow[2], aG[2];
    uint32_t aSw[2];
#pragma unroll
    for (int h = 0; h < 2; h++) {
        int u = t + 256 * h;
        aRow[h] = u >> 3;
        aG[h]   = u & 7;
        aSw[h]  = (uint32_t)(aRow[h] * 128 + ((aG[h] ^ (aRow[h] & 7)) << 4));
    }

    float aF[16];
    auto ldgA = [&](int c) {
#pragma unroll
        for (int h = 0; h < 2; h++) {
            const float4* p = (const float4*)(x + (size_t)(mBase + aRow[h]) * K_DIM
                                              + c * BK + aG[h] * 8);
            float4 u0 = p[0], u1 = p[1];
            aF[h*8+0] = u0.x; aF[h*8+1] = u0.y; aF[h*8+2] = u0.z; aF[h*8+3] = u0.w;
            aF[h*8+4] = u1.x; aF[h*8+5] = u1.y; aF[h*8+6] = u1.z; aF[h*8+7] = u1.w;
        }
    };
    auto stsA = [&](int buf) {
#pragma unroll
        for (int h = 0; h < 2; h++) {
            uint32_t pk[4];
#pragma unroll
            for (int j = 0; j < 4; j++) {
                __half2 hh = __floats2half2_rn(aF[h*8 + 2*j], aF[h*8 + 2*j + 1]);
                pk[j] = *(uint32_t*)&hh;
            }
            *(uint4*)(smem + buf * 8192 + aSw[h]) = make_uint4(pk[0], pk[1], pk[2], pk[3]);
        }
    };
    auto cpB = [&](int c) {
        const int kB = c * BK;
        const uint32_t bufB = sb + S_BOP + (c & 1) * 32768;
#pragma unroll
        for (int r = 0; r < 8; r++) {
            int u   = t + GTHREADS * r;          // 0..2047
            int row = u >> 3;
            int gg  = u & 7;
            uint32_t sw = (uint32_t)(row * 128 + ((gg ^ (row & 7)) << 4));
            cp_async16(bufB + sw, g_bh + (size_t)row * K_DIM + kB + gg * 8);
        }
        cp_commit();
    };

    float acc[2][8][4];
#pragma unroll
    for (int mi = 0; mi < 2; mi++)
#pragma unroll
        for (int ni = 0; ni < 8; ni++)
#pragma unroll
            for (int r = 0; r < 4; r++) acc[mi][ni][r] = 0.0f;

    ldgA(0);
    cpB(0);
    cpB(1);
    stsA(0);
    ldgA(1);

    const int NCH = K_DIM / BK;   // 4
    for (int c = 0; c < NCH; c++) {
        if (c < NCH - 1) cp_wait1(); else cp_wait0();
        __syncthreads();

        if (c + 1 < NCH) stsA((c + 1) & 1);
        if (c + 2 < NCH) ldgA(c + 2);

        const uint32_t bufA = sb + (c & 1) * 8192;
        const uint32_t bufB = sb + S_BOP + (c & 1) * 32768;

#pragma unroll
        for (int ks = 0; ks < 4; ks++) {
            const uint32_t seg = (uint32_t)((ks * 2 + khalf) ^ kx) << 4;

            uint32_t ah[2][4], bh[4][4];
#pragma unroll
            for (int mi = 0; mi < 2; mi++)
                ldsm4(ah[mi][0], ah[mi][1], ah[mi][2], ah[mi][3], bufA + mByte[mi] + seg);
#pragma unroll
            for (int ni = 0; ni < 4; ni++)
                ldsm4(bh[ni][0], bh[ni][1], bh[ni][2], bh[ni][3], bufB + nByte[ni] + seg);

#pragma unroll
            for (int mi = 0; mi < 2; mi++)
#pragma unroll
                for (int ni = 0; ni < 8; ni++)
                    mma_fp16(acc[mi][ni], ah[mi], bh[ni >> 1][ni & 1], bh[ni >> 1][(ni & 1) + 2]);
        }

        __syncthreads();
        if (c + 2 < NCH) cpB(c + 2);
    }

    // Epilogue: stage D transposed in smem [n][m] (stride EPAD -> conflict-free)
    float* sOut = (float*)smem;
    const int crow = lane >> 2;
    const int ccol = (lane & 3) * 2;
#pragma unroll
    for (int mi = 0; mi < 2; mi++)
#pragma unroll
        for (int ni = 0; ni < 8; ni++) {
            int m0 = wm + mi * 16 + crow;
            int n0 = wn + ni * 8 + ccol;
            sOut[(n0    ) * EPAD + m0    ] = acc[mi][ni][0];
            sOut[(n0 + 1) * EPAD + m0    ] = acc[mi][ni][1];
            sOut[(n0    ) * EPAD + m0 + 8] = acc[mi][ni][2];
            sOut[(n0 + 1) * EPAD + m0 + 8] = acc[mi][ni][3];
        }
    __syncthreads();

    // Coalesced global write: g_xpt[(g*256 + n)*512 + i]
    const int g     = mBase >> 9;
    const int iBase = mBase & 511;
#pragma unroll
    for (int r = 0; r < 16; r++) {
        int u   = t + GTHREADS * r;          // 0..4095
        int row = u >> 4;                    // n 0..255
        int pos = u & 15;                    // float4 within 64 m
        float4 v = *(float4*)&sOut[row * EPAD + pos * 4];
        float* dst = g_xpt + ((size_t)(g * N_PROJ + row)) * NPG + iBase + pos * 4;
        *(float4*)dst = v;
    }
}

// ---------------------------------------------------------------------------
// Kernel 3: per-warp bitonic sort of 512 values + quantile gather + write.
//   In-register exchanges use the alu/fma split:
//     c0 = (up ? min : max)(a,b)   -> 1 FMNMX (alu pipe)
//     other = (a+b) - c0           -> 2 FFMA-imm (fma pipe)
// ---------------------------------------------------------------------------
template<int KK, int J>
__device__ __forceinline__ void bstep(float (&v)[16], int lane) {
    if constexpr (J >= 16) {
#pragma unroll
        for (int r = 0; r < 16; r++) {
            float pv = __shfl_xor_sync(0xffffffffu, v[r], J >> 4);
            int i = lane * 16 + r;
            bool takeMin = ((i & KK) == 0) == ((i & J) == 0);
            v[r] = takeMin ? fminf(v[r], pv) : fmaxf(v[r], pv);
        }
    } else {
#pragma unroll
        for (int r = 0; r < 16; r++) {
            if ((r & J) == 0) {
                int i = lane * 16 + r;
                bool up = ((i & KK) == 0);
                float a = v[r], b = v[r | J];
                float s  = __fmaf_rn(a, 1.0f, b);          // fma pipe
                float c0 = up ? fminf(a, b) : fmaxf(a, b); // 1 FMNMX (alu)
                v[r]     = c0;
                v[r | J] = __fmaf_rn(c0, -1.0f, s);        // fma pipe
            }
        }
    }
}
template<int KK, int J>
__device__ __forceinline__ void bmerge(float (&v)[16], int lane) {
    bstep<KK, J>(v, lane);
    if constexpr (J > 1) bmerge<KK, J / 2>(v, lane);
}

__global__ void __launch_bounds__(256)
sort_quant_kernel(const float* __restrict__ cw, float* __restrict__ out) {
    __shared__ float sbuf[8][512];      // sorted columns, one per warp
    __shared__ float qbuf[8][264];      // quantiles staged (padded stride)
    __shared__ int   qidx[NUM_Q];

    const int t = threadIdx.x;
    qidx[t] = (int)floorf(cw[t] * (float)(NPG - 1));   // matches jnp.floor(cw*511)
    __syncthreads();

    const int w    = t >> 5;
    const int lane = t & 31;
    const int col  = blockIdx.x * 8 + w;               // (g,p) column id

    float v[16];
    const float4* src = (const float4*)(g_xpt + (size_t)col * NPG);
#pragma unroll
    for (int q = 0; q < 4; q++) {
        float4 f = src[lane * 4 + q];
        v[q * 4 + 0] = f.x; v[q * 4 + 1] = f.y;
        v[q * 4 + 2] = f.z; v[q * 4 + 3] = f.w;
    }

    bmerge<2, 1>(v, lane);
    bmerge<4, 2>(v, lane);
    bmerge<8, 4>(v, lane);
    bmerge<16, 8>(v, lane);
    bmerge<32, 16>(v, lane);
    bmerge<64, 32>(v, lane);
    bmerge<128, 64>(v, lane);
    bmerge<256, 128>(v, lane);
    bmerge<512, 256>(v, lane);

    float4* dst = (float4*)sbuf[w];
#pragma unroll
    for (int q = 0; q < 4; q++)
        dst[lane * 4 + q] = make_float4(v[q * 4 + 0], v[q * 4 + 1], v[q * 4 + 2], v[q * 4 + 3]);
    __syncwarp();

#pragma unroll
    for (int s = 0; s < 8; s++) {
        int q = lane + 32 * s;
        qbuf[w][q] = sbuf[w][qidx[q]] * (1.0f / 256.0f);
    }
    __syncthreads();

    const int gg    = blockIdx.x >> 5;
    const int pbase = (blockIdx.x * 8) & 255;
    const size_t obase = (size_t)gg * (NUM_Q * N_PROJ) + pbase;
#pragma unroll
    for (int s = 0; s < 8; s++) {
        int e  = t + 256 * s;          // 0..2047
        int q  = e >> 3;
        int wp = e & 7;
        out[obase + (size_t)q * N_PROJ + wp] = qbuf[wp][q];
    }
}

// ---------------------------------------------------------------------------
// kernel_launch: convp -> fp16 HMMA gemm -> sort/quantile (graph-capturable)
// ---------------------------------------------------------------------------
extern "C" void kernel_launch(void* const* d_in, const int* in_sizes, int n_in,
                              void* d_out, int out_size) {
    const float* x    = (const float*)d_in[0];   // [131072, 256] f32
    const float* proj = (const float*)d_in[1];   // [256, 256]    f32
    const float* cw   = (const float*)d_in[2];   // [256]         f32
    float* out = (float*)d_out;                  // [256, 65536]  f32

    cudaFuncSetAttribute(gemm_hmma_kernel,
                         cudaFuncAttributeMaxDynamicSharedMemorySize,
                         GEMM_SMEM);

    convp_kernel<<<N_PROJ, K_DIM>>>(proj);
    gemm_hmma_kernel<<<M_NODES / BM, GTHREADS, GEMM_SMEM>>>(x);
    sort_quant_kernel<<<(NUM_G * N_PROJ) / 8, 256>>>(cw, out);
}

// round 15
// speedup vs baseline: 2.5565x; 1.1843x over previous
#include <cuda_runtime.h>
#include <cuda_fp16.h>
#include <stdint.h>

// Problem constants (fixed shapes)
#define M_NODES   131072
#define K_DIM     256
#define N_PROJ    256
#define NUM_G     256
#define NPG       512          // nodes per graph
#define NUM_Q     256

// Scratch (device globals; no allocation allowed in kernel_launch)
__device__ __half g_bh[N_PROJ * K_DIM];                    // proj^T fp16 [n][k]
__device__ float g_xpt[(size_t)NUM_G * N_PROJ * NPG];      // xp transposed [g][p][i]

// ---------------------------------------------------------------------------
// PTX helpers (base ISA only — no sm_103a-gated features)
// ---------------------------------------------------------------------------
__device__ __forceinline__ uint32_t smem_u32(const void* p) {
    uint32_t a;
    asm("{ .reg .u64 t; cvta.to.shared.u64 t, %1; cvt.u32.u64 %0, t; }" : "=r"(a) : "l"(p));
    return a;
}
__device__ __forceinline__ void cp_async16(uint32_t saddr, const void* gptr) {
    asm volatile("cp.async.cg.shared.global [%0], [%1], 16;" :: "r"(saddr), "l"(gptr));
}
__device__ __forceinline__ void cp_commit() { asm volatile("cp.async.commit_group;"); }
__device__ __forceinline__ void cp_wait1()  { asm volatile("cp.async.wait_group 1;"); }
__device__ __forceinline__ void cp_wait0()  { asm volatile("cp.async.wait_group 0;"); }

__device__ __forceinline__ void ldsm4(uint32_t& r0, uint32_t& r1, uint32_t& r2, uint32_t& r3,
                                      uint32_t addr) {
    asm volatile("ldmatrix.sync.aligned.m8n8.x4.shared.b16 {%0,%1,%2,%3}, [%4];"
                 : "=r"(r0), "=r"(r1), "=r"(r2), "=r"(r3) : "r"(addr));
}
__device__ __forceinline__ void mma_fp16(float* c, const uint32_t* a, uint32_t b0, uint32_t b1) {
    asm volatile("mma.sync.aligned.m16n8k16.row.col.f32.f16.f16.f32 "
                 "{%0,%1,%2,%3}, {%4,%5,%6,%7}, {%8,%9}, {%0,%1,%2,%3};"
                 : "+f"(c[0]), "+f"(c[1]), "+f"(c[2]), "+f"(c[3])
                 : "r"(a[0]), "r"(a[1]), "r"(a[2]), "r"(a[3]), "r"(b0), "r"(b1));
}

// ---------------------------------------------------------------------------
// Kernel 1: convert + transpose proj -> B[n][k] fp16 (K-major); tiny.
// ---------------------------------------------------------------------------
__global__ void convp_kernel(const float* __restrict__ proj) {
    int n = blockIdx.x, k = threadIdx.x;
    g_bh[n * K_DIM + k] = __float2half_rn(proj[(size_t)k * N_PROJ + n]);
}

// ---------------------------------------------------------------------------
// Kernel 2: single-pass fp16 HMMA GEMM, BM=64 BN=256 BK=64. (unchanged, R14)
// ---------------------------------------------------------------------------
#define BM 64
#define BN 256
#define BK 64
#define GTHREADS 256
#define S_BOP   16384    // bOp[2]: 256 rows x 128B = 32768 each
#define GEMM_SMEM 81920
#define EPAD 68          // epilogue staging stride (floats)

__global__ void __launch_bounds__(GTHREADS, 2)
gemm_hmma_kernel(const float* __restrict__ x) {
    extern __shared__ char smem[];
    const uint32_t sb = smem_u32(smem);

    const int t     = threadIdx.x;
    const int lane  = t & 31;
    const int wid   = t >> 5;
    const int mBase = blockIdx.x * BM;
    const int wm    = (wid >> 2) * 32;   // warp tile 32 x 64
    const int wn    = (wid & 3) * 64;

    const int rsel  = lane & 15;
    const int khalf = lane >> 4;
    const int kx    = lane & 7;

    uint32_t mByte[2], nByte[4];
#pragma unroll
    for (int mi = 0; mi < 2; mi++) mByte[mi] = (uint32_t)(wm + mi * 16 + rsel) * 128;
#pragma unroll
    for (int ni = 0; ni < 4; ni++) nByte[ni] = (uint32_t)(wn + ni * 16 + rsel) * 128;

    int aRow[2], aG[2];
    uint32_t aSw[2];
#pragma unroll
    for (int h = 0; h < 2; h++) {
        int u = t + 256 * h;
        aRow[h] = u >> 3;
        aG[h]   = u & 7;
        aSw[h]  = (uint32_t)(aRow[h] * 128 + ((aG[h] ^ (aRow[h] & 7)) << 4));
    }

    float aF[16];
    auto ldgA = [&](int c) {
#pragma unroll
        for (int h = 0; h < 2; h++) {
            const float4* p = (const float4*)(x + (size_t)(mBase + aRow[h]) * K_DIM
                                              + c * BK + aG[h] * 8);
            float4 u0 = p[0], u1 = p[1];
            aF[h*8+0] = u0.x; aF[h*8+1] = u0.y; aF[h*8+2] = u0.z; aF[h*8+3] = u0.w;
            aF[h*8+4] = u1.x; aF[h*8+5] = u1.y; aF[h*8+6] = u1.z; aF[h*8+7] = u1.w;
        }
    };
    auto stsA = [&](int buf) {
#pragma unroll
        for (int h = 0; h < 2; h++) {
            uint32_t pk[4];
#pragma unroll
            for (int j = 0; j < 4; j++) {
                __half2 hh = __floats2half2_rn(aF[h*8 + 2*j], aF[h*8 + 2*j + 1]);
                pk[j] = *(uint32_t*)&hh;
            }
            *(uint4*)(smem + buf * 8192 + aSw[h]) = make_uint4(pk[0], pk[1], pk[2], pk[3]);
        }
    };
    auto cpB = [&](int c) {
        const int kB = c * BK;
        const uint32_t bufB = sb + S_BOP + (c & 1) * 32768;
#pragma unroll
        for (int r = 0; r < 8; r++) {
            int u   = t + GTHREADS * r;          // 0..2047
            int row = u >> 3;
            int gg  = u & 7;
            uint32_t sw = (uint32_t)(row * 128 + ((gg ^ (row & 7)) << 4));
            cp_async16(bufB + sw, g_bh + (size_t)row * K_DIM + kB + gg * 8);
        }
        cp_commit();
    };

    float acc[2][8][4];
#pragma unroll
    for (int mi = 0; mi < 2; mi++)
#pragma unroll
        for (int ni = 0; ni < 8; ni++)
#pragma unroll
            for (int r = 0; r < 4; r++) acc[mi][ni][r] = 0.0f;

    ldgA(0);
    cpB(0);
    cpB(1);
    stsA(0);
    ldgA(1);

    const int NCH = K_DIM / BK;   // 4
    for (int c = 0; c < NCH; c++) {
        if (c < NCH - 1) cp_wait1(); else cp_wait0();
        __syncthreads();

        if (c + 1 < NCH) stsA((c + 1) & 1);
        if (c + 2 < NCH) ldgA(c + 2);

        const uint32_t bufA = sb + (c & 1) * 8192;
        const uint32_t bufB = sb + S_BOP + (c & 1) * 32768;

#pragma unroll
        for (int ks = 0; ks < 4; ks++) {
            const uint32_t seg = (uint32_t)((ks * 2 + khalf) ^ kx) << 4;

            uint32_t ah[2][4], bh[4][4];
#pragma unroll
            for (int mi = 0; mi < 2; mi++)
                ldsm4(ah[mi][0], ah[mi][1], ah[mi][2], ah[mi][3], bufA + mByte[mi] + seg);
#pragma unroll
            for (int ni = 0; ni < 4; ni++)
                ldsm4(bh[ni][0], bh[ni][1], bh[ni][2], bh[ni][3], bufB + nByte[ni] + seg);

#pragma unroll
            for (int mi = 0; mi < 2; mi++)
#pragma unroll
                for (int ni = 0; ni < 8; ni++)
                    mma_fp16(acc[mi][ni], ah[mi], bh[ni >> 1][ni & 1], bh[ni >> 1][(ni & 1) + 2]);
        }

        __syncthreads();
        if (c + 2 < NCH) cpB(c + 2);
    }

    // Epilogue: stage D transposed in smem [n][m] (stride EPAD -> conflict-free)
    float* sOut = (float*)smem;
    const int crow = lane >> 2;
    const int ccol = (lane & 3) * 2;
#pragma unroll
    for (int mi = 0; mi < 2; mi++)
#pragma unroll
        for (int ni = 0; ni < 8; ni++) {
            int m0 = wm + mi * 16 + crow;
            int n0 = wn + ni * 8 + ccol;
            sOut[(n0    ) * EPAD + m0    ] = acc[mi][ni][0];
            sOut[(n0 + 1) * EPAD + m0    ] = acc[mi][ni][1];
            sOut[(n0    ) * EPAD + m0 + 8] = acc[mi][ni][2];
            sOut[(n0 + 1) * EPAD + m0 + 8] = acc[mi][ni][3];
        }
    __syncthreads();

    // Coalesced global write: g_xpt[(g*256 + n)*512 + i]
    const int g     = mBase >> 9;
    const int iBase = mBase & 511;
#pragma unroll
    for (int r = 0; r < 16; r++) {
        int u   = t + GTHREADS * r;          // 0..4095
        int row = u >> 4;                    // n 0..255
        int pos = u & 15;                    // float4 within 64 m
        float4 v = *(float4*)&sOut[row * EPAD + pos * 4];
        float* dst = g_xpt + ((size_t)(g * N_PROJ + row)) * NPG + iBase + pos * 4;
        *(float4*)dst = v;
    }
}

// ---------------------------------------------------------------------------
// Kernel 3: packed half2 bitonic sort — each warp sorts TWO columns at once
//   (col pair packed lane-wise into half2). Identical network topology to the
//   fp32 version; every SHFL/HMNMX2 processes both columns -> ~2x fewer ops
//   per column. Quantile gather unpacks lo/hi, scales in fp32.
// ---------------------------------------------------------------------------
__device__ __forceinline__ __half2 h2min(__half2 a, __half2 b) { return __hmin2(a, b); }
__device__ __forceinline__ __half2 h2max(__half2 a, __half2 b) { return __hmax2(a, b); }

template<int KK, int J>
__device__ __forceinline__ void bstep2(__half2 (&v)[16], int lane) {
    if constexpr (J >= 16) {
#pragma unroll
        for (int r = 0; r < 16; r++) {
            uint32_t pv = __shfl_xor_sync(0xffffffffu, *(uint32_t*)&v[r], J >> 4);
            __half2 p = *(__half2*)&pv;
            int i = lane * 16 + r;
            bool takeMin = ((i & KK) == 0) == ((i & J) == 0);
            v[r] = takeMin ? h2min(v[r], p) : h2max(v[r], p);
        }
    } else {
#pragma unroll
        for (int r = 0; r < 16; r++) {
            if ((r & J) == 0) {
                int i = lane * 16 + r;
                bool up = ((i & KK) == 0);
                __half2 a = v[r], b = v[r | J];
                v[r]     = up ? h2min(a, b) : h2max(a, b);
                v[r | J] = up ? h2max(a, b) : h2min(a, b);
            }
        }
    }
}
template<int KK, int J>
__device__ __forceinline__ void bmerge2(__half2 (&v)[16], int lane) {
    bstep2<KK, J>(v, lane);
    if constexpr (J > 1) bmerge2<KK, J / 2>(v, lane);
}

__global__ void __launch_bounds__(256)
sort_quant_kernel(const float* __restrict__ cw, float* __restrict__ out) {
    __shared__ uint32_t sbuf[8][512];   // sorted half2 columns, one pair per warp
    __shared__ uint32_t qbuf[8][264];   // half2 quantiles staged (padded stride)
    __shared__ int      qidx[NUM_Q];

    const int t = threadIdx.x;
    qidx[t] = (int)floorf(cw[t] * (float)(NPG - 1));   // matches jnp.floor(cw*511)
    __syncthreads();

    const int w    = t >> 5;
    const int lane = t & 31;
    // CTA covers 16 consecutive (g,p) columns; warp w owns cols base+2w, base+2w+1
    const int col0 = blockIdx.x * 16 + 2 * w;

    // Load both columns, pack to half2 (lo = col0, hi = col0+1)
    __half2 v[16];
    const float4* s0 = (const float4*)(g_xpt + (size_t)col0 * NPG);
    const float4* s1 = (const float4*)(g_xpt + (size_t)(col0 + 1) * NPG);
#pragma unroll
    for (int q = 0; q < 4; q++) {
        float4 a = s0[lane * 4 + q];
        float4 b = s1[lane * 4 + q];
        v[q * 4 + 0] = __floats2half2_rn(a.x, b.x);
        v[q * 4 + 1] = __floats2half2_rn(a.y, b.y);
        v[q * 4 + 2] = __floats2half2_rn(a.z, b.z);
        v[q * 4 + 3] = __floats2half2_rn(a.w, b.w);
    }

    // Bitonic sort (ascending in each half independently), 512 elems across warp
    bmerge2<2, 1>(v, lane);
    bmerge2<4, 2>(v, lane);
    bmerge2<8, 4>(v, lane);
    bmerge2<16, 8>(v, lane);
    bmerge2<32, 16>(v, lane);
    bmerge2<64, 32>(v, lane);
    bmerge2<128, 64>(v, lane);
    bmerge2<256, 128>(v, lane);
    bmerge2<512, 256>(v, lane);

    // Stage sorted pair column in smem (rank e at sbuf[w][e])
    uint4* dst = (uint4*)sbuf[w];
#pragma unroll
    for (int q = 0; q < 4; q++)
        dst[lane * 4 + q] = make_uint4(*(uint32_t*)&v[q * 4 + 0], *(uint32_t*)&v[q * 4 + 1],
                                       *(uint32_t*)&v[q * 4 + 2], *(uint32_t*)&v[q * 4 + 3]);
    __syncwarp();

    // Gather quantiles (still packed)
#pragma unroll
    for (int s = 0; s < 8; s++) {
        int q = lane + 32 * s;
        qbuf[w][q] = sbuf[w][qidx[q]];
    }
    __syncthreads();

    // Coalesced write: out[g*65536 + q*256 + p], 16 consecutive p per CTA
    const int gg    = blockIdx.x >> 4;
    const int pbase = (blockIdx.x * 16) & 255;
    const size_t obase = (size_t)gg * (NUM_Q * N_PROJ) + pbase;
#pragma unroll
    for (int s = 0; s < 16; s++) {
        int e  = t + 256 * s;          // 0..4095
        int q  = e >> 4;
        int wp = e & 15;
        uint32_t pair = qbuf[wp >> 1][q];
        __half h = (wp & 1) ? __high2half(*(__half2*)&pair) : __low2half(*(__half2*)&pair);
        out[obase + (size_t)q * N_PROJ + wp] = __half2float(h) * (1.0f / 256.0f);
    }
}

// ---------------------------------------------------------------------------
// kernel_launch: convp -> fp16 HMMA gemm -> half2 sort/quantile
// ---------------------------------------------------------------------------
extern "C" void kernel_launch(void* const* d_in, const int* in_sizes, int n_in,
                              void* d_out, int out_size) {
    const float* x    = (const float*)d_in[0];   // [131072, 256] f32
    const float* proj = (const float*)d_in[1];   // [256, 256]    f32
    const float* cw   = (const float*)d_in[2];   // [256]         f32
    float* out = (float*)d_out;                  // [256, 65536]  f32

    cudaFuncSetAttribute(gemm_hmma_kernel,
                         cudaFuncAttributeMaxDynamicSharedMemorySize,
                         GEMM_SMEM);

    convp_kernel<<<N_PROJ, K_DIM>>>(proj);
    gemm_hmma_kernel<<<M_NODES / BM, GTHREADS, GEMM_SMEM>>>(x);
    sort_quant_kernel<<<(NUM_G * N_PROJ) / 16, 256>>>(cw, out);
}